// round 17
// baseline (speedup 1.0000x reference)
#include <cuda_runtime.h>
#include <cstddef>
#include <cstdint>

#define NN 100000
#define DD 128
#define FF 64
#define SS 16
#define NPB 32              // nodes per block (divides 100000)
#define WPAD 132            // weight smem row stride (132 ≡ 4 mod 32 -> conflict-free phases)
#define APAD 132            // agg smem row stride (same property)
#define FPAD 68             // feat-kernel row stride (68 ≡ 4 mod 32)

// Scratch embeddings (allocation-free rule: __device__ globals)
__device__ float g_x0[(size_t)NN * DD];
__device__ float g_x1[(size_t)NN * DD];

// Packed dual-fp32 FMA / ADD (PTX-only forms on sm_10x)
__device__ __forceinline__ void ffma2(unsigned long long& acc,
                                      unsigned long long a,
                                      unsigned long long b)
{
    asm("fma.rn.f32x2 %0, %1, %2, %0;" : "+l"(acc) : "l"(a), "l"(b));
}
__device__ __forceinline__ void fadd2(unsigned long long& a, unsigned long long b)
{
    asm("add.rn.f32x2 %0, %0, %1;" : "+l"(a) : "l"(b));
}
__device__ __forceinline__ float2 up2(unsigned long long v)
{
    float2 f;
    asm("mov.b64 {%0, %1}, %2;" : "=f"(f.x), "=f"(f.y) : "l"(v));
    return f;
}
__device__ __forceinline__ float pair_hsum(unsigned long long v)
{
    float2 f = up2(v);
    return f.x + f.y;
}
// 16B non-coherent global load reinterpreted as two u64 lanes
__device__ __forceinline__ ulonglong2 ldg128(const float* p)
{
    float4 v = __ldg((const float4*)p);
    ulonglong2 r;
    asm("mov.b64 %0, {%2, %3}; mov.b64 %1, {%4, %5};"
        : "=l"(r.x), "=l"(r.y) : "f"(v.x), "f"(v.y), "f"(v.z), "f"(v.w));
    return r;
}

// ---------------------------------------------------------------------------
// Kernel 1: x0 = feat @ w_feat^T      feat:[N,64], w_feat:[128,64]
// 256 threads, 4x4 register tile: dg=tid>>3 (d = dg+32j), ng=tid&7 (node = ng+8m)
// ---------------------------------------------------------------------------
__global__ __launch_bounds__(256) void feat_kernel(
    const float* __restrict__ feat,
    const float* __restrict__ wf,
    float* __restrict__ xout)
{
    __shared__ float ws[DD * FPAD];
    __shared__ float fs[NPB * FPAD];

    const int tid  = threadIdx.x;     // 0..255
    const int dg   = tid >> 3;        // 0..31
    const int ng   = tid & 7;         // 0..7
    const int base = blockIdx.x * NPB;

    // stage w_feat (float4 into padded rows)
    for (int q = tid; q < DD * FF / 4; q += 256) {
        float4 v = __ldg(((const float4*)wf) + q);
        int dd = q >> 4, f = (q & 15) << 2;
        *(float4*)&ws[dd * FPAD + f] = v;
    }
    // stage features (float4 into padded rows)
    for (int q = tid; q < NPB * FF / 4; q += 256) {
        float4 v = __ldg(((const float4*)(feat + (size_t)base * FF)) + q);
        int nn = q >> 4, f = (q & 15) << 2;
        *(float4*)&fs[nn * FPAD + f] = v;
    }
    __syncthreads();

    unsigned long long acc2[4][4];
#pragma unroll
    for (int j = 0; j < 4; j++)
#pragma unroll
        for (int m = 0; m < 4; m++) acc2[j][m] = 0ull;

#pragma unroll
    for (int f4 = 0; f4 < FF / 4; f4++) {
        ulonglong2 wq[4], aq[4];
#pragma unroll
        for (int j = 0; j < 4; j++)
            wq[j] = *(const ulonglong2*)&ws[(dg + 32 * j) * FPAD + 4 * f4];   // LDS.128
#pragma unroll
        for (int m = 0; m < 4; m++)
            aq[m] = *(const ulonglong2*)&fs[(ng + 8 * m) * FPAD + 4 * f4];    // LDS.128
#pragma unroll
        for (int j = 0; j < 4; j++)
#pragma unroll
            for (int m = 0; m < 4; m++) {
                ffma2(acc2[j][m], wq[j].x, aq[m].x);
                ffma2(acc2[j][m], wq[j].y, aq[m].y);
            }
    }
#pragma unroll
    for (int j = 0; j < 4; j++)
#pragma unroll
        for (int m = 0; m < 4; m++)
            xout[(size_t)(base + ng + 8 * m) * DD + dg + 32 * j] = pair_hsum(acc2[j][m]);
}

// ---------------------------------------------------------------------------
// Kernel 2: one GraphSAGE layer  (256 threads, 4x4 register-tiled GEMM)
//   agg = (x[n] + sum_s x[idx[n,s]]) / 17
//   h   = relu(agg @ w^T);  out = h / max(||h||, 1e-12)
// ---------------------------------------------------------------------------
__global__ __launch_bounds__(256) void layer_kernel(
    const float* __restrict__ xin,
    const int*   __restrict__ nidx,
    const float* __restrict__ w,
    float* __restrict__ xout)
{
    extern __shared__ float sm[];
    float* ws   = sm;                        // 128*132 floats
    float* agg  = ws + DD * WPAD;            // 32*132 floats (reused as h after GEMM)
    float* invn = agg + NPB * APAD;          // 32
    int*   idxs = (int*)(invn + NPB);        // 32*16 ints (16B-aligned)

    const int tid  = threadIdx.x;            // 0..255
    const int dg   = tid >> 3;               // 0..31
    const int ng   = tid & 7;                // 0..7
    const int base = blockIdx.x * NPB;

    // stage weights as float4 into padded rows
    for (int q = tid; q < DD * DD / 4; q += 256) {
        float4 v = __ldg(((const float4*)w) + q);
        int dd = q >> 5, k = (q & 31) << 2;
        *(float4*)&ws[dd * WPAD + k] = v;
    }
    // stage neighbour indices (int4): 128 int4 total
    if (tid < NPB * SS / 4)
        ((int4*)idxs)[tid] = __ldg(((const int4*)(nidx + (size_t)base * SS)) + tid);
    __syncthreads();

    // ---- aggregation: 8 warps x 4 nodes; lane owns one 16B chunk ----
    {
        const int wrp  = tid >> 5;
        const int lane = tid & 31;
        const int coff = lane << 2;

#pragma unroll
        for (int k = 0; k < 4; k++) {
            const int node = wrp * 4 + k;
            const int4* ip = (const int4*)&idxs[node * SS];
            int4 q0 = ip[0], q1 = ip[1], q2 = ip[2], q3 = ip[3];
            int rows[16] = { q0.x, q0.y, q0.z, q0.w,
                             q1.x, q1.y, q1.z, q1.w,
                             q2.x, q2.y, q2.z, q2.w,
                             q3.x, q3.y, q3.z, q3.w };

            ulonglong2 accA = ldg128(&xin[(size_t)(base + node) * DD + coff]);
            ulonglong2 accB = ldg128(&xin[(size_t)rows[8] * DD + coff]);
#pragma unroll
            for (int j = 0; j < 8; j++) {
                ulonglong2 va = ldg128(&xin[(size_t)rows[j] * DD + coff]);
                fadd2(accA.x, va.x);
                fadd2(accA.y, va.y);
            }
#pragma unroll
            for (int j = 9; j < 16; j++) {
                ulonglong2 vb = ldg128(&xin[(size_t)rows[j] * DD + coff]);
                fadd2(accB.x, vb.x);
                fadd2(accB.y, vb.y);
            }
            fadd2(accA.x, accB.x);
            fadd2(accA.y, accB.y);

            float2 lo = up2(accA.x), hi = up2(accA.y);
            const float C = 1.0f / 17.0f;
            float4 r = { lo.x * C, lo.y * C, hi.x * C, hi.y * C };
            *(float4*)&agg[node * APAD + coff] = r;            // STS.128 conflict-free
        }
    }
    __syncthreads();

    // ---- GEMM 4x4 register tile: h[ng+8m][dg+32j] = agg . w ----
    unsigned long long acc2[4][4];
#pragma unroll
    for (int j = 0; j < 4; j++)
#pragma unroll
        for (int m = 0; m < 4; m++) acc2[j][m] = 0ull;

#pragma unroll
    for (int k4 = 0; k4 < DD / 4; k4++) {
        ulonglong2 wq[4], aq[4];
#pragma unroll
        for (int j = 0; j < 4; j++)
            wq[j] = *(const ulonglong2*)&ws[(dg + 32 * j) * WPAD + 4 * k4];   // LDS.128
#pragma unroll
        for (int m = 0; m < 4; m++)
            aq[m] = *(const ulonglong2*)&agg[(ng + 8 * m) * APAD + 4 * k4];   // LDS.128
#pragma unroll
        for (int j = 0; j < 4; j++)
#pragma unroll
            for (int m = 0; m < 4; m++) {
                ffma2(acc2[j][m], wq[j].x, aq[m].x);
                ffma2(acc2[j][m], wq[j].y, aq[m].y);
            }
    }
    __syncthreads();   // everyone done reading agg

    // ---- ReLU + store h back to agg (banks 4*ng+dg: all 32 distinct) ----
#pragma unroll
    for (int j = 0; j < 4; j++)
#pragma unroll
        for (int m = 0; m < 4; m++)
            agg[(ng + 8 * m) * APAD + dg + 32 * j] =
                fmaxf(pair_hsum(acc2[j][m]), 0.0f);
    __syncthreads();

    // ---- L2 norm: 8 threads per node; node-rotated reads ----
    {
        int node = tid >> 3, l8 = tid & 7;
        float sum = 0.0f;
#pragma unroll
        for (int j = 0; j < 16; j++) {
            int dim = (l8 + 8 * (j + node)) & 127;
            float v = agg[node * APAD + dim];
            sum += v * v;
        }
        sum += __shfl_down_sync(0xffffffffu, sum, 4, 8);
        sum += __shfl_down_sync(0xffffffffu, sum, 2, 8);
        sum += __shfl_down_sync(0xffffffffu, sum, 1, 8);
        if (l8 == 0)
            invn[node] = 1.0f / fmaxf(sqrtf(sum), 1e-12f);
    }
    __syncthreads();

    // ---- normalized write-out: vectorized (LDS.128 + STG.128) ----
    {
        const int wrp  = tid >> 5;
        const int lane = tid & 31;
        const int coff = lane << 2;
#pragma unroll
        for (int k = 0; k < 4; k++) {
            const int node = wrp * 4 + k;
            float4 v = *(const float4*)&agg[node * APAD + coff];
            float s = invn[node];
            float4 r = { v.x * s, v.y * s, v.z * s, v.w * s };
            *(float4*)&xout[(size_t)(base + node) * DD + coff] = r;
        }
    }
}

// ---------------------------------------------------------------------------

static const int LAYER_SMEM = (DD * WPAD + NPB * APAD + NPB) * 4 + NPB * SS * 4; // 86,656 B

extern "C" void kernel_launch(void* const* d_in, const int* in_sizes, int n_in,
                              void* d_out, int out_size)
{
    const float* feat  = (const float*)d_in[0];   // [N,64]
    const float* wfeat = (const float*)d_in[1];   // [128,64]
    const float* w1    = (const float*)d_in[2];   // [128,128]
    const float* w2    = (const float*)d_in[3];   // [128,128]
    const int*   n1    = (const int*)  d_in[4];   // [N,16]
    const int*   n2    = (const int*)  d_in[5];   // [N,16]
    float*       out   = (float*)d_out;           // [N,128]

    (void)in_sizes; (void)n_in; (void)out_size;

    void *p0, *p1;
    cudaGetSymbolAddress(&p0, g_x0);
    cudaGetSymbolAddress(&p1, g_x1);
    float* x0 = (float*)p0;
    float* x1 = (float*)p1;

    cudaFuncSetAttribute(layer_kernel,
                         cudaFuncAttributeMaxDynamicSharedMemorySize, LAYER_SMEM);

    const int blocks = NN / NPB;   // 3125

    feat_kernel<<<blocks, 256>>>(feat, wfeat, x0);
    layer_kernel<<<blocks, 256, LAYER_SMEM>>>(x0, n1, w1, x1);
    layer_kernel<<<blocks, 256, LAYER_SMEM>>>(x1, n2, w2, out);
}